// round 11
// baseline (speedup 1.0000x reference)
#include <cuda_runtime.h>
#include <cuda_bf16.h>

// ============================================================================
// 2-layer LSTM (B=256, T=512, I=64, H=512) + head on sm_100 base via
// mma.sync.m16n8k16 bf16, 3-term split precision, fp32 accum.
// R11: 128 persistent CTAs x 512 thr (16 warps/SM, 4/SMSP) to fix the
// latency bound seen at 8 warps (issue=15%, tensor=42%). 4-way K-split:
// 4 groups x (2x2 warps, m32xn32 each); partials in 2x4x16KB smem, summed
// in the cell update. Merged phases (L1(t-1) + L0(t), 513 barriers) kept.
// __launch_bounds__(512,1) caps regs at 128/thread; gemm_seg unroll 2.
// ============================================================================

typedef unsigned u32;

#define NCTA 128
#define NTHR 512
#define NQ0  36     // layer-0 k16 tiles: 32 (h0) + 4 (x)
#define NQ1  64     // layer-1 k16 tiles: 32 (h0 cur) + 32 (h1 prev)
#define SMEM_DYN (32768 * 4)   // 2 outputs x 4 K-groups x 64x64 fp32 = 128KB

// ---------------- device scratch (static) -----------------------------------
__device__ __align__(16) __nv_bfloat16 g_WP0[128 * NQ0 * 512];
__device__ __align__(16) __nv_bfloat16 g_WP1[128 * NQ1 * 512];
__device__ __align__(16) __nv_bfloat16 g_XP[512 * 4 * 32 * 256];
__device__ __align__(16) __nv_bfloat16 g_HB[2 * 2 * 32 * 32 * 256];
__device__ float g_C[2 * 512 * 256];
__device__ float g_h1fin[512 * 256];
__device__ float g_bias[2 * 2048];
__device__ u32 g_barCnt;
__device__ volatile u32 g_barGen;

// ---------------- helpers ---------------------------------------------------
__device__ __forceinline__ void grid_barrier() {
    __syncthreads();
    if (threadIdx.x == 0) {
        u32 gen = g_barGen;
        __threadfence();
        if (atomicAdd(&g_barCnt, 1u) == NCTA - 1u) {
            g_barCnt = 0u;
            __threadfence();
            g_barGen = gen + 1u;
        } else {
            while (g_barGen == gen) { }
        }
        __threadfence();
    }
    __syncthreads();
}

__device__ __forceinline__ float sigm(float x) { return 1.0f / (1.0f + expf(-x)); }

__device__ __forceinline__ void mma4(float* d, uint4 a, u32 b0, u32 b1) {
    asm volatile(
        "mma.sync.aligned.m16n8k16.row.col.f32.bf16.bf16.f32 "
        "{%0,%1,%2,%3}, {%4,%5,%6,%7}, {%8,%9}, {%0,%1,%2,%3};"
        : "+f"(d[0]), "+f"(d[1]), "+f"(d[2]), "+f"(d[3])
        : "r"(a.x), "r"(a.y), "r"(a.z), "r"(a.w), "r"(b0), "r"(b1));
}

// One contiguous K segment of NQ k16-steps for an m32 x n32 warp tile.
// Unroll 2: latency hiding now comes from 16 warps, not per-warp MLP
// (keeps register demand under the 128/thread cap).
template <int NQ>
__device__ __forceinline__ void gemm_seg(
    const uint4* __restrict__ A0p, const uint4* __restrict__ A1p,
    const uint4* __restrict__ Bp, float acc[2][4][4])
{
#pragma unroll 2
    for (int q = 0; q < NQ; q++) {
        uint4 a0h = __ldg(A0p);     uint4 a0l = __ldg(A0p + 1);
        uint4 a1h = __ldg(A1p);     uint4 a1l = __ldg(A1p + 1);
        uint4 b0  = __ldcg(Bp);
        uint4 b1  = __ldcg(Bp + 32);
        uint4 b2  = __ldcg(Bp + 64);
        uint4 b3  = __ldcg(Bp + 96);
        mma4(acc[0][0], a0h, b0.x, b0.y);
        mma4(acc[0][0], a0h, b0.z, b0.w);
        mma4(acc[0][0], a0l, b0.x, b0.y);
        mma4(acc[0][1], a0h, b1.x, b1.y);
        mma4(acc[0][1], a0h, b1.z, b1.w);
        mma4(acc[0][1], a0l, b1.x, b1.y);
        mma4(acc[0][2], a0h, b2.x, b2.y);
        mma4(acc[0][2], a0h, b2.z, b2.w);
        mma4(acc[0][2], a0l, b2.x, b2.y);
        mma4(acc[0][3], a0h, b3.x, b3.y);
        mma4(acc[0][3], a0h, b3.z, b3.w);
        mma4(acc[0][3], a0l, b3.x, b3.y);
        mma4(acc[1][0], a1h, b0.x, b0.y);
        mma4(acc[1][0], a1h, b0.z, b0.w);
        mma4(acc[1][0], a1l, b0.x, b0.y);
        mma4(acc[1][1], a1h, b1.x, b1.y);
        mma4(acc[1][1], a1h, b1.z, b1.w);
        mma4(acc[1][1], a1l, b1.x, b1.y);
        mma4(acc[1][2], a1h, b2.x, b2.y);
        mma4(acc[1][2], a1h, b2.z, b2.w);
        mma4(acc[1][2], a1l, b2.x, b2.y);
        mma4(acc[1][3], a1h, b3.x, b3.y);
        mma4(acc[1][3], a1h, b3.z, b3.w);
        mma4(acc[1][3], a1l, b3.x, b3.y);
        A0p += 64; A1p += 64; Bp += 1024;
    }
}

// Store one warp's partial D tile into its gsm region.
__device__ __forceinline__ void store_partials(
    float acc[2][4][4], float* gout, int wm, int wn, int lane)
{
#pragma unroll
    for (int mi = 0; mi < 2; mi++)
#pragma unroll
        for (int ni = 0; ni < 4; ni++) {
            int lr = (wm * 2 + mi) * 16 + (lane >> 2);
            int cl = (wn * 4 + ni) * 8 + (lane & 3) * 2;
            float* d = acc[mi][ni];
            *(float2*)&gout[lr * 64 + cl]       = make_float2(d[0], d[1]);
            *(float2*)&gout[(lr + 8) * 64 + cl] = make_float2(d[2], d[3]);
        }
}

// Cell update for one layer; sums 4 K-group partials (stride 4096 floats).
__device__ __forceinline__ void cell_upd(
    const float* gbase, int lay, int pwv, int m_cta, int n_cta,
    int tid, bool fin)
{
    float* Cp = g_C + lay * 131072;
    const float* bp = g_bias + lay * 2048;
#pragma unroll
    for (int e = 0; e < 2; e++) {
        int cell = e * NTHR + tid;            // 1024 cells, 2 per thread
        int jl = cell >> 6, bl = cell & 63;
        int j = m_cta * 16 + jl;
        int b = n_cta * 64 + bl;
        float g4[4];
#pragma unroll
        for (int gi = 0; gi < 4; gi++) {
            int o = (jl * 4 + gi) * 64 + bl;
            g4[gi] = gbase[o] + gbase[4096 + o] + gbase[8192 + o] + gbase[12288 + o]
                   + __ldg(bp + gi * 512 + j);
        }
        float c = Cp[j * 256 + b];
        c = sigm(g4[1]) * c + sigm(g4[0]) * tanhf(g4[2]);
        Cp[j * 256 + b] = c;
        float hv = sigm(g4[3]) * tanhf(c);
        __nv_bfloat16 hh = __float2bfloat16_rn(hv);
        __nv_bfloat16 hl = __float2bfloat16_rn(hv - __bfloat162float(hh));
        int n8 = n_cta * 8 + (bl >> 3), nl = bl & 7;
        int lane2 = nl * 4 + ((jl & 7) >> 1);
        int r = jl >> 3, hb = jl & 1;
        int blk = ((pwv * 2 + lay) * 32 + m_cta) * 32 + n8;
        __nv_bfloat16* p = g_HB + blk * 256 + lane2 * 8 + r * 2 + hb;
        p[0] = hh;
        p[4] = hl;
        if (fin) g_h1fin[j * 256 + b] = hv;
    }
}

// ---------------- the persistent kernel -------------------------------------
extern __shared__ __align__(16) float gsm[];   // [out 2][grp 4][64*64]

__global__ void __launch_bounds__(NTHR, 1) lstm_all(
    const float* __restrict__ x,
    const float* __restrict__ Wih0, const float* __restrict__ Whh0,
    const float* __restrict__ bih0, const float* __restrict__ bhh0,
    const float* __restrict__ Wih1, const float* __restrict__ Whh1,
    const float* __restrict__ bih1, const float* __restrict__ bhh1,
    const float* __restrict__ Wout, const float* __restrict__ bout,
    float* __restrict__ out)
{
    const int tid  = threadIdx.x;
    const int wid  = tid >> 5;
    const int lane = tid & 31;
    const int gtid = blockIdx.x * NTHR + tid;
    const int NT   = NCTA * NTHR;

    // ======== prep: identical math/layouts to R10 winner ========
    for (int i = gtid; i < 128 * NQ0 * 512; i += NT) {
        int bi = i >> 9, off = i & 511;
        int l = off >> 4, rem = off & 15;
        int sect = rem >> 3, r = (rem >> 1) & 3, h = rem & 1;
        int mt = bi / NQ0, q = bi % NQ0;
        int lr = (l >> 2) + (r & 1) * 8;
        int c  = (l & 3) * 2 + h + (r >> 1) * 8;
        int R  = mt * 16 + lr;
        int GR = (R & 3) * 512 + (R >> 2);
        int k  = q * 16 + c;
        float w = (k < 512) ? Whh0[GR * 512 + k] : Wih0[GR * 64 + (k - 512)];
        __nv_bfloat16 hh = __float2bfloat16_rn(w);
        g_WP0[i] = sect ? __float2bfloat16_rn(w - __bfloat162float(hh)) : hh;
    }
    for (int i = gtid; i < 128 * NQ1 * 512; i += NT) {
        int bi = i >> 9, off = i & 511;
        int l = off >> 4, rem = off & 15;
        int sect = rem >> 3, r = (rem >> 1) & 3, h = rem & 1;
        int mt = bi / NQ1, q = bi % NQ1;
        int lr = (l >> 2) + (r & 1) * 8;
        int c  = (l & 3) * 2 + h + (r >> 1) * 8;
        int R  = mt * 16 + lr;
        int GR = (R & 3) * 512 + (R >> 2);
        int k  = q * 16 + c;
        float w = (k < 512) ? Wih1[GR * 512 + k] : Whh1[GR * 512 + (k - 512)];
        __nv_bfloat16 hh = __float2bfloat16_rn(w);
        g_WP1[i] = sect ? __float2bfloat16_rn(w - __bfloat162float(hh)) : hh;
    }
    for (int i = gtid; i < 512 * 4 * 32 * 256; i += NT) {
        int bi = i >> 8, off = i & 255;
        int l = off >> 3, rem = off & 7;
        int sect = rem >> 2, r = (rem >> 1) & 1, h = rem & 1;
        int n8 = bi & 31, rest = bi >> 5;
        int qp = rest & 3, t = rest >> 2;
        int kl = r * 8 + (l & 3) * 2 + h;
        int nl = l >> 2;
        int b  = n8 * 8 + nl, ii = qp * 16 + kl;
        float v = x[(b * 512 + t) * 64 + ii];
        __nv_bfloat16 hh = __float2bfloat16_rn(v);
        g_XP[i] = sect ? __float2bfloat16_rn(v - __bfloat162float(hh)) : hh;
    }
    for (int i = gtid; i < 2 * 2 * 32 * 32 * 256; i += NT)
        g_HB[i] = __float2bfloat16(0.f);
    for (int i = gtid; i < 2 * 512 * 256; i += NT) g_C[i] = 0.f;
    for (int i = gtid; i < 2048; i += NT) {
        g_bias[i]        = bih0[i] + bhh0[i];
        g_bias[2048 + i] = bih1[i] + bhh1[i];
    }

    grid_barrier();

    // ======== merged mainloop: phase t = { L1(t-1), L0(t) } ========
    const int m_cta = blockIdx.x >> 2;
    const int n_cta = blockIdx.x & 3;
    const int grp = wid >> 2;              // K-quarter group, 0..3
    const int wl  = wid & 3;
    const int wm  = wl >> 1;
    const int wn  = wl & 1;
    const int mt0 = m_cta * 4 + wm * 2;
    const int n8b = n_cta * 8 + wn * 4;

    const uint4* WP0v = (const uint4*)g_WP0;
    const uint4* WP1v = (const uint4*)g_WP1;
    const uint4* XPv  = (const uint4*)g_XP;
    const uint4* HBv  = (const uint4*)g_HB;
    float* gout0 = gsm + grp * 4096;           // L1(t-1) partials
    float* gout1 = gsm + 16384 + grp * 4096;   // L0(t)   partials

    for (int t = 0; t <= 512; t++) {
        const int u = t & 1, v = u ^ 1;
        const bool do1 = (t >= 1);
        const bool do0 = (t <= 511);

        if (do1) {
            // L1(t-1): q0-31 = h0(t-1)@(v,0), q32-63 = h1(t-2)@(u,1)
            float acc[2][4][4] = {};
            const uint4* A0 = WP1v + (mt0 * NQ1) * 64 + lane * 2;
            const uint4* A1 = WP1v + ((mt0 + 1) * NQ1) * 64 + lane * 2;
            const uint4* B0 = HBv + ((v * 2 + 0) * 1024 + n8b) * 32 + lane;
            const uint4* B1 = HBv + ((u * 2 + 1) * 1024 + n8b) * 32 + lane;
            if (grp == 0)      gemm_seg<16>(A0,           A1,           B0, acc);
            else if (grp == 1) gemm_seg<16>(A0 + 16 * 64, A1 + 16 * 64, B0 + 16 * 1024, acc);
            else if (grp == 2) gemm_seg<16>(A0 + 32 * 64, A1 + 32 * 64, B1, acc);
            else               gemm_seg<16>(A0 + 48 * 64, A1 + 48 * 64, B1 + 16 * 1024, acc);
            store_partials(acc, gout0, wm, wn, lane);
        }
        if (do0) {
            // L0(t): q0-31 = h0(t-1)@(v,0), q32-35 = x(t)
            float acc[2][4][4] = {};
            const uint4* A0 = WP0v + (mt0 * NQ0) * 64 + lane * 2;
            const uint4* A1 = WP0v + ((mt0 + 1) * NQ0) * 64 + lane * 2;
            const uint4* Bh = HBv + ((v * 2 + 0) * 1024 + n8b) * 32 + lane;
            if (grp == 0)      gemm_seg<9>(A0,           A1,           Bh, acc);
            else if (grp == 1) gemm_seg<9>(A0 + 9 * 64,  A1 + 9 * 64,  Bh + 9 * 1024, acc);
            else if (grp == 2) gemm_seg<9>(A0 + 18 * 64, A1 + 18 * 64, Bh + 18 * 1024, acc);
            else {
                gemm_seg<5>(A0 + 27 * 64, A1 + 27 * 64, Bh + 27 * 1024, acc);
                gemm_seg<4>(A0 + 32 * 64, A1 + 32 * 64,
                            XPv + (t * 4 * 32 + n8b) * 32 + lane, acc);
            }
            store_partials(acc, gout1, wm, wn, lane);
        }
        __syncthreads();

        if (do1) cell_upd(gsm,         1, v, m_cta, n_cta, tid, t == 512);
        if (do0) cell_upd(gsm + 16384, 0, u, m_cta, n_cta, tid, false);

        grid_barrier();
    }

    // ======== head ========
    if (blockIdx.x == 0 && tid < 256) {
        int b = tid;
        float a = __ldg(bout);
#pragma unroll 8
        for (int j = 0; j < 512; j++)
            a += fmaxf(__ldcg(g_h1fin + j * 256 + b), 0.f) * __ldg(Wout + j);
        out[b] = a;
    }
}

// ---------------- launch ----------------------------------------------------
extern "C" void kernel_launch(void* const* d_in, const int* in_sizes, int n_in,
                              void* d_out, int out_size) {
    (void)in_sizes; (void)n_in; (void)out_size;
    const float* x    = (const float*)d_in[0];
    const float* Wih0 = (const float*)d_in[1];
    const float* Whh0 = (const float*)d_in[2];
    const float* bih0 = (const float*)d_in[3];
    const float* bhh0 = (const float*)d_in[4];
    const float* Wih1 = (const float*)d_in[5];
    const float* Whh1 = (const float*)d_in[6];
    const float* bih1 = (const float*)d_in[7];
    const float* bhh1 = (const float*)d_in[8];
    const float* Wout = (const float*)d_in[9];
    const float* bout = (const float*)d_in[10];
    float* out = (float*)d_out;

    cudaFuncSetAttribute(lstm_all, cudaFuncAttributeMaxDynamicSharedMemorySize, SMEM_DYN);
    lstm_all<<<NCTA, NTHR, SMEM_DYN>>>(x, Wih0, Whh0, bih0, bhh0,
                                       Wih1, Whh1, bih1, bhh1, Wout, bout, out);
}